// round 2
// baseline (speedup 1.0000x reference)
#include <cuda_runtime.h>
#include <math.h>

#define N_NODES 20000
#define N_EDGES 640000
#define ND 128
#define ED 64
#define HID 128
#define K1 (2*ND+ED)   // 320

// ---- scratch (device globals: no allocations allowed) ----
__device__ float g_aggr[(size_t)N_NODES * HID];   // segment-summed edge messages
__device__ float g_cacc[(size_t)N_NODES * 3];     // coord update accumulator

typedef unsigned long long u64;

__device__ __forceinline__ float silu_f(float x){ return x / (1.0f + __expf(-x)); }
__device__ __forceinline__ u64 splat2(float a){ u64 r; asm("mov.b64 %0, {%1, %1};" : "=l"(r) : "f"(a)); return r; }
__device__ __forceinline__ u64 pack2(float lo, float hi){ u64 r; asm("mov.b64 %0, {%1, %2};" : "=l"(r) : "f"(lo), "f"(hi)); return r; }
__device__ __forceinline__ void fma2(u64& d, u64 a, u64 b){ asm("fma.rn.f32x2 %0, %1, %2, %3;" : "=l"(d) : "l"(a), "l"(b), "l"(d)); }
__device__ __forceinline__ float2 unpack2(u64 v){ float2 f; asm("mov.b64 {%0, %1}, %2;" : "=f"(f.x), "=f"(f.y) : "l"(v)); return f; }

// ------------------------------------------------------------------
// zero scratch before each replay
// ------------------------------------------------------------------
__global__ void zero_kernel()
{
    const int total = N_NODES * HID + N_NODES * 3;
    int i = blockIdx.x * blockDim.x + threadIdx.x;
    if (i < total) {
        if (i < N_NODES * HID) g_aggr[i] = 0.0f;
        else                   g_cacc[i - N_NODES * HID] = 0.0f;
    }
}

// ------------------------------------------------------------------
// Edge kernel: fused gather -> edge MLP -> scatter(msg) -> coord MLP -> scatter(coord)
// Tile: 128 edges x 128 hid per block, 256 threads,
// micro-tile 8 edges x 8 cols per thread (packed f32x2 over column pairs).
// ------------------------------------------------------------------
#define TILE_E 128
#define KC 32
#define KC_PAD 36

struct __align__(16) EdgeSmem {
    float As[2][TILE_E][KC_PAD];  // gathered edge_feat chunks   (36 KB)
    float Bs[2][KC][HID];         // weight chunks; reused for cW1 (32 KB)
    float Hs[TILE_E][HID + 4];    // h1 then edge_message        (67.6 KB)
    int   src[TILE_E];
    int   dst[TILE_E];
    float eb1[HID];
    float eb2[HID];
    float cb1[64];
    float cw2[64];
    float cb2;
};

__global__ __launch_bounds__(256, 1)
void edge_kernel(const float* __restrict__ node_feat,
                 const int*   __restrict__ edge_index,
                 const float* __restrict__ edge_attr,
                 const float* __restrict__ coords,
                 const float* __restrict__ eW1, const float* __restrict__ eb1,
                 const float* __restrict__ eW2, const float* __restrict__ eb2,
                 const float* __restrict__ cW1, const float* __restrict__ cb1,
                 const float* __restrict__ cW2, const float* __restrict__ cb2)
{
    extern __shared__ char smem_raw[];
    EdgeSmem& sm = *reinterpret_cast<EdgeSmem*>(smem_raw);

    const int tid = threadIdx.x;
    const int tx = tid & 15;        // column group: cols tx*8 .. tx*8+7
    const int ty = tid >> 4;        // edge group:   edges ty*8 .. ty*8+7
    const int e0 = blockIdx.x * TILE_E;

    if (tid < TILE_E) {
        sm.src[tid] = edge_index[e0 + tid];
        sm.dst[tid] = edge_index[N_EDGES + e0 + tid];
        sm.eb1[tid] = eb1[tid];
        sm.eb2[tid] = eb2[tid];
        if (tid < 64) { sm.cb1[tid] = cb1[tid]; sm.cw2[tid] = cW2[tid]; }
        if (tid == 0) sm.cb2 = cb2[0];
    }
    __syncthreads();

    // ---- staging helpers ----
    const int se = tid >> 1;   // A-staging: edge index
    const int sh = tid & 1;    // which 16-float half of the 32-wide chunk
    float4 ra[4];
    auto ldA = [&](int kb) {
        const int kg = kb + sh * 16;
        const float* p;
        if (kg < ND)          p = node_feat + (size_t)sm.src[se] * ND + kg;
        else if (kg < 2*ND)   p = node_feat + (size_t)sm.dst[se] * ND + (kg - ND);
        else                  p = edge_attr + (size_t)(e0 + se) * ED + (kg - 2*ND);
        ra[0] = *(const float4*)(p);
        ra[1] = *(const float4*)(p + 4);
        ra[2] = *(const float4*)(p + 8);
        ra[3] = *(const float4*)(p + 12);
    };
    auto stA = [&](int buf) {
        float* q = &sm.As[buf][se][sh * 16];
        *(float4*)(q)      = ra[0];
        *(float4*)(q + 4)  = ra[1];
        *(float4*)(q + 8)  = ra[2];
        *(float4*)(q + 12) = ra[3];
    };
    float4 rb[4];
    auto ldB = [&](const float* W, int kb) {
        #pragma unroll
        for (int r = 0; r < 4; r++) {
            const int f = tid + r * 256;
            const int k = f >> 5, n4 = f & 31;
            rb[r] = *(const float4*)(W + (size_t)(kb + k) * HID + n4 * 4);
        }
    };
    auto stB = [&](int buf) {
        #pragma unroll
        for (int r = 0; r < 4; r++) {
            const int f = tid + r * 256;
            const int k = f >> 5, n4 = f & 31;
            *(float4*)(&sm.Bs[buf][k][n4 * 4]) = rb[r];
        }
    };

    // =========================== GEMM1: [128,320]@[320,128] ===========================
    u64 acc[8][4];
    #pragma unroll
    for (int i = 0; i < 8; i++)
        #pragma unroll
        for (int j = 0; j < 4; j++) acc[i][j] = 0ull;

    ldA(0); ldB(eW1, 0); stA(0); stB(0);
    __syncthreads();

    const int NC1 = K1 / KC;   // 10
    for (int c = 0; c < NC1; ++c) {
        const int cur = c & 1;
        if (c + 1 < NC1) { ldA((c + 1) * KC); ldB(eW1, (c + 1) * KC); }
        #pragma unroll 4
        for (int kk = 0; kk < KC; ++kk) {
            ulonglong2 b01 = *(const ulonglong2*)&sm.Bs[cur][kk][tx * 8];
            ulonglong2 b23 = *(const ulonglong2*)&sm.Bs[cur][kk][tx * 8 + 4];
            #pragma unroll
            for (int i = 0; i < 8; i++) {
                u64 ap = splat2(sm.As[cur][ty * 8 + i][kk]);
                fma2(acc[i][0], ap, b01.x);
                fma2(acc[i][1], ap, b01.y);
                fma2(acc[i][2], ap, b23.x);
                fma2(acc[i][3], ap, b23.y);
            }
        }
        if (c + 1 < NC1) { const int nxt = (c + 1) & 1; stA(nxt); stB(nxt); }
        __syncthreads();
    }

    // bias + SiLU -> Hs (h1)
    #pragma unroll
    for (int i = 0; i < 8; i++) {
        const int e = ty * 8 + i;
        #pragma unroll
        for (int j = 0; j < 4; j++) {
            const int n = tx * 8 + j * 2;
            float2 v = unpack2(acc[i][j]);
            v.x = silu_f(v.x + sm.eb1[n]);
            v.y = silu_f(v.y + sm.eb1[n + 1]);
            *(float2*)&sm.Hs[e][n] = v;
        }
    }

    // =========================== GEMM2: [128,128]@[128,128] ===========================
    u64 acc2[8][4];
    #pragma unroll
    for (int i = 0; i < 8; i++)
        #pragma unroll
        for (int j = 0; j < 4; j++) acc2[i][j] = 0ull;

    ldB(eW2, 0); stB(0);
    __syncthreads();

    const int NC2 = HID / KC;  // 4
    for (int c = 0; c < NC2; ++c) {
        const int cur = c & 1;
        if (c + 1 < NC2) ldB(eW2, (c + 1) * KC);
        const int kb = c * KC;
        #pragma unroll 4
        for (int kk = 0; kk < KC; ++kk) {
            ulonglong2 b01 = *(const ulonglong2*)&sm.Bs[cur][kk][tx * 8];
            ulonglong2 b23 = *(const ulonglong2*)&sm.Bs[cur][kk][tx * 8 + 4];
            #pragma unroll
            for (int i = 0; i < 8; i++) {
                u64 ap = splat2(sm.Hs[ty * 8 + i][kb + kk]);
                fma2(acc2[i][0], ap, b01.x);
                fma2(acc2[i][1], ap, b01.y);
                fma2(acc2[i][2], ap, b23.x);
                fma2(acc2[i][3], ap, b23.y);
            }
        }
        if (c + 1 < NC2) { const int nxt = (c + 1) & 1; stB(nxt); }
        __syncthreads();
    }

    // bias + SiLU -> edge_message; scatter atomics + store to Hs (overwrite h1)
    float2 msg2[8][4];
    #pragma unroll
    for (int i = 0; i < 8; i++) {
        #pragma unroll
        for (int j = 0; j < 4; j++) {
            const int n = tx * 8 + j * 2;
            float2 v = unpack2(acc2[i][j]);
            v.x = silu_f(v.x + sm.eb2[n]);
            v.y = silu_f(v.y + sm.eb2[n + 1]);
            msg2[i][j] = v;
        }
    }
    #pragma unroll
    for (int i = 0; i < 8; i++) {
        const int e = ty * 8 + i;
        float* ag = g_aggr + (size_t)sm.dst[e] * HID + tx * 8;
        #pragma unroll
        for (int j = 0; j < 4; j++) {
            atomicAdd(ag + j * 2,     msg2[i][j].x);
            atomicAdd(ag + j * 2 + 1, msg2[i][j].y);
            *(float2*)&sm.Hs[e][tx * 8 + j * 2] = msg2[i][j];
        }
    }

    // stage cW1 [128,64] into the (now free) Bs region
    float* cw1s = &sm.Bs[0][0][0];  // 8192 floats = exactly 2*KC*HID
    #pragma unroll
    for (int r = 0; r < 8; r++) {
        const int f4 = tid + r * 256;
        *(float4*)(cw1s + f4 * 4) = *(const float4*)(cW1 + f4 * 4);
    }
    __syncthreads();

    // =========================== coord MLP + scatter ===========================
    // thread pair per edge: half handles 32 of the 64 hidden units
    {
        const int e = tid >> 1;
        const int half = tid & 1;
        u64 s[16];
        #pragma unroll
        for (int q = 0; q < 16; q++)
            s[q] = pack2(sm.cb1[half * 32 + 2 * q], sm.cb1[half * 32 + 2 * q + 1]);

        #pragma unroll 4
        for (int k = 0; k < HID; k++) {
            u64 hp = splat2(sm.Hs[e][k]);
            const ulonglong2* row = (const ulonglong2*)(cw1s + k * 64 + half * 32);
            #pragma unroll
            for (int q = 0; q < 8; q++) {
                ulonglong2 bb = row[q];
                fma2(s[2 * q],     hp, bb.x);
                fma2(s[2 * q + 1], hp, bb.y);
            }
        }
        float p = 0.0f;
        #pragma unroll
        for (int q = 0; q < 16; q++) {
            float2 v = unpack2(s[q]);
            const int u = half * 32 + 2 * q;
            p += silu_f(v.x) * sm.cw2[u] + silu_f(v.y) * sm.cw2[u + 1];
        }
        p += __shfl_xor_sync(0xffffffffu, p, 1);
        if (half == 0) {
            const float cw = p + sm.cb2;
            const int isrc = sm.src[e], idst = sm.dst[e];
            const float dx = coords[isrc * 3 + 0] - coords[idst * 3 + 0];
            const float dy = coords[isrc * 3 + 1] - coords[idst * 3 + 1];
            const float dz = coords[isrc * 3 + 2] - coords[idst * 3 + 2];
            const float nrm = sqrtf(dx * dx + dy * dy + dz * dz) + 1e-8f;
            const float w = cw / nrm;
            atomicAdd(&g_cacc[idst * 3 + 0], dx * w);
            atomicAdd(&g_cacc[idst * 3 + 1], dy * w);
            atomicAdd(&g_cacc[idst * 3 + 2], dz * w);
        }
    }
}

// ------------------------------------------------------------------
// Node kernel: node MLP (residual) + coord finalize
// Tile: 64 nodes x 128 cols, 256 threads, micro 4x8.
// ------------------------------------------------------------------
#define TILE_N 64

struct __align__(16) NodeSmem {
    float As[2][TILE_N][KC_PAD];  // 18 KB
    float Bs[2][KC][HID];         // 32 KB
    float Hs[TILE_N][HID + 4];    // 33.8 KB
    float nb1[HID];
    float nb2[HID];
};

__global__ __launch_bounds__(256, 1)
void node_kernel(const float* __restrict__ node_feat,
                 const float* __restrict__ coords,
                 const float* __restrict__ nW1, const float* __restrict__ nb1,
                 const float* __restrict__ nW2, const float* __restrict__ nb2,
                 float* __restrict__ out)
{
    extern __shared__ char smem_raw[];
    NodeSmem& sm = *reinterpret_cast<NodeSmem*>(smem_raw);

    const int tid = threadIdx.x;
    const int tx = tid & 15;
    const int ty = tid >> 4;
    const int n0 = blockIdx.x * TILE_N;

    if (tid < HID) { sm.nb1[tid] = nb1[tid]; sm.nb2[tid] = nb2[tid]; }
    __syncthreads();

    const int se = tid >> 2;    // node row for A-staging (0..63)
    const int sq = tid & 3;     // 8-float quarter of the 32-chunk
    float4 ra[2];
    auto ldA = [&](int kb) {
        const int kg = kb + sq * 8;
        const int node = min(n0 + se, N_NODES - 1);
        const float* p = (kg < ND) ? node_feat + (size_t)node * ND + kg
                                   : g_aggr + (size_t)node * HID + (kg - ND);
        ra[0] = *(const float4*)(p);
        ra[1] = *(const float4*)(p + 4);
    };
    auto stA = [&](int buf) {
        float* q = &sm.As[buf][se][sq * 8];
        *(float4*)(q)     = ra[0];
        *(float4*)(q + 4) = ra[1];
    };
    float4 rb[4];
    auto ldB = [&](const float* W, int kb) {
        #pragma unroll
        for (int r = 0; r < 4; r++) {
            const int f = tid + r * 256;
            const int k = f >> 5, n4 = f & 31;
            rb[r] = *(const float4*)(W + (size_t)(kb + k) * HID + n4 * 4);
        }
    };
    auto stB = [&](int buf) {
        #pragma unroll
        for (int r = 0; r < 4; r++) {
            const int f = tid + r * 256;
            const int k = f >> 5, n4 = f & 31;
            *(float4*)(&sm.Bs[buf][k][n4 * 4]) = rb[r];
        }
    };

    // ---- GEMM1: [64,256]@[256,128] ----
    u64 acc[4][4];
    #pragma unroll
    for (int i = 0; i < 4; i++)
        #pragma unroll
        for (int j = 0; j < 4; j++) acc[i][j] = 0ull;

    ldA(0); ldB(nW1, 0); stA(0); stB(0);
    __syncthreads();

    const int NC1 = (ND + HID) / KC;  // 8
    for (int c = 0; c < NC1; ++c) {
        const int cur = c & 1;
        if (c + 1 < NC1) { ldA((c + 1) * KC); ldB(nW1, (c + 1) * KC); }
        #pragma unroll 4
        for (int kk = 0; kk < KC; ++kk) {
            ulonglong2 b01 = *(const ulonglong2*)&sm.Bs[cur][kk][tx * 8];
            ulonglong2 b23 = *(const ulonglong2*)&sm.Bs[cur][kk][tx * 8 + 4];
            #pragma unroll
            for (int i = 0; i < 4; i++) {
                u64 ap = splat2(sm.As[cur][ty * 4 + i][kk]);
                fma2(acc[i][0], ap, b01.x);
                fma2(acc[i][1], ap, b01.y);
                fma2(acc[i][2], ap, b23.x);
                fma2(acc[i][3], ap, b23.y);
            }
        }
        if (c + 1 < NC1) { const int nxt = (c + 1) & 1; stA(nxt); stB(nxt); }
        __syncthreads();
    }

    #pragma unroll
    for (int i = 0; i < 4; i++) {
        const int e = ty * 4 + i;
        #pragma unroll
        for (int j = 0; j < 4; j++) {
            const int n = tx * 8 + j * 2;
            float2 v = unpack2(acc[i][j]);
            v.x = silu_f(v.x + sm.nb1[n]);
            v.y = silu_f(v.y + sm.nb1[n + 1]);
            *(float2*)&sm.Hs[e][n] = v;
        }
    }

    // ---- GEMM2: [64,128]@[128,128] ----
    u64 acc2[4][4];
    #pragma unroll
    for (int i = 0; i < 4; i++)
        #pragma unroll
        for (int j = 0; j < 4; j++) acc2[i][j] = 0ull;

    ldB(nW2, 0); stB(0);
    __syncthreads();

    const int NC2 = HID / KC;  // 4
    for (int c = 0; c < NC2; ++c) {
        const int cur = c & 1;
        if (c + 1 < NC2) ldB(nW2, (c + 1) * KC);
        const int kb = c * KC;
        #pragma unroll 4
        for (int kk = 0; kk < KC; ++kk) {
            ulonglong2 b01 = *(const ulonglong2*)&sm.Bs[cur][kk][tx * 8];
            ulonglong2 b23 = *(const ulonglong2*)&sm.Bs[cur][kk][tx * 8 + 4];
            #pragma unroll
            for (int i = 0; i < 4; i++) {
                u64 ap = splat2(sm.Hs[ty * 4 + i][kb + kk]);
                fma2(acc2[i][0], ap, b01.x);
                fma2(acc2[i][1], ap, b01.y);
                fma2(acc2[i][2], ap, b23.x);
                fma2(acc2[i][3], ap, b23.y);
            }
        }
        if (c + 1 < NC2) { const int nxt = (c + 1) & 1; stB(nxt); }
        __syncthreads();
    }

    // residual output
    #pragma unroll
    for (int i = 0; i < 4; i++) {
        const int node = n0 + ty * 4 + i;
        if (node < N_NODES) {
            #pragma unroll
            for (int j = 0; j < 4; j++) {
                const int n = tx * 8 + j * 2;
                float2 v = unpack2(acc2[i][j]);
                out[(size_t)node * ND + n]     = v.x + sm.nb2[n]     + node_feat[(size_t)node * ND + n];
                out[(size_t)node * ND + n + 1] = v.y + sm.nb2[n + 1] + node_feat[(size_t)node * ND + n + 1];
            }
        }
    }

    // coord finalize
    for (int idx = tid; idx < TILE_N * 3; idx += 256) {
        const int node = n0 + idx / 3;
        const int c = idx % 3;
        if (node < N_NODES)
            out[(size_t)N_NODES * ND + node * 3 + c] = coords[node * 3 + c] + g_cacc[node * 3 + c];
    }
}

// ------------------------------------------------------------------
extern "C" void kernel_launch(void* const* d_in, const int* in_sizes, int n_in,
                              void* d_out, int out_size)
{
    const float* node_feat  = (const float*)d_in[0];
    const int*   edge_index = (const int*)  d_in[1];
    const float* edge_attr  = (const float*)d_in[2];
    const float* coords     = (const float*)d_in[3];
    const float* eW1 = (const float*)d_in[4];
    const float* eb1 = (const float*)d_in[5];
    const float* eW2 = (const float*)d_in[6];
    const float* eb2 = (const float*)d_in[7];
    const float* nW1 = (const float*)d_in[8];
    const float* nb1 = (const float*)d_in[9];
    const float* nW2 = (const float*)d_in[10];
    const float* nb2 = (const float*)d_in[11];
    const float* cW1 = (const float*)d_in[12];
    const float* cb1 = (const float*)d_in[13];
    const float* cW2 = (const float*)d_in[14];
    const float* cb2 = (const float*)d_in[15];
    float* out = (float*)d_out;

    cudaFuncSetAttribute(edge_kernel, cudaFuncAttributeMaxDynamicSharedMemorySize, (int)sizeof(EdgeSmem));
    cudaFuncSetAttribute(node_kernel, cudaFuncAttributeMaxDynamicSharedMemorySize, (int)sizeof(NodeSmem));

    const int ztotal = N_NODES * HID + N_NODES * 3;
    zero_kernel<<<(ztotal + 255) / 256, 256>>>();

    edge_kernel<<<N_EDGES / TILE_E, 256, sizeof(EdgeSmem)>>>(
        node_feat, edge_index, edge_attr, coords,
        eW1, eb1, eW2, eb2, cW1, cb1, cW2, cb2);

    node_kernel<<<(N_NODES + TILE_N - 1) / TILE_N, 256, sizeof(NodeSmem)>>>(
        node_feat, coords, nW1, nb1, nW2, nb2, out);
}

// round 9
// speedup vs baseline: 3.3061x; 3.3061x over previous
#include <cuda_runtime.h>
#include <cuda_bf16.h>
#include <cstdint>
#include <math.h>

#define N_NODES 20000
#define N_EDGES 640000
#define ND 128
#define ED 64
#define HID 128

__device__ float g_aggr[(size_t)N_NODES * HID];
__device__ float g_cacc[(size_t)N_NODES * 4];
__device__ float g_e1t[128 * 320];   // eW1^T [n][k]
__device__ float g_e2t[128 * 128];   // eW2^T [n][k]
__device__ float g_c1t[64 * 128];    // cW1^T [n][k]

typedef unsigned long long u64;

__device__ __forceinline__ float silu_f(float x){ return x / (1.0f + __expf(-x)); }
__device__ __forceinline__ uint32_t smem_u32(const void* p){
    uint32_t a; asm("{ .reg .u64 t; cvta.to.shared.u64 t, %1; cvt.u32.u64 %0, t; }" : "=r"(a) : "l"(p)); return a;
}
__device__ __forceinline__ void ldmx4(uint32_t* r, uint32_t a){
    asm volatile("ldmatrix.sync.aligned.m8n8.x4.shared.b16 {%0,%1,%2,%3},[%4];"
        : "=r"(r[0]),"=r"(r[1]),"=r"(r[2]),"=r"(r[3]) : "r"(a));
}
__device__ __forceinline__ void mma_bf16(float* d, const uint32_t* a, uint32_t b0, uint32_t b1){
    asm volatile("mma.sync.aligned.m16n8k16.row.col.f32.bf16.bf16.f32 "
        "{%0,%1,%2,%3},{%4,%5,%6,%7},{%8,%9},{%0,%1,%2,%3};"
        : "+f"(d[0]),"+f"(d[1]),"+f"(d[2]),"+f"(d[3])
        : "r"(a[0]),"r"(a[1]),"r"(a[2]),"r"(a[3]),"r"(b0),"r"(b1));
}
__device__ __forceinline__ void packp(float x, float y, uint32_t& h, uint32_t& l){
    __nv_bfloat162 hh = __floats2bfloat162_rn(x, y);
    __nv_bfloat162 ll = __floats2bfloat162_rn(x - __bfloat162float(hh.x), y - __bfloat162float(hh.y));
    h = *(uint32_t*)&hh; l = *(uint32_t*)&ll;
}
__device__ __forceinline__ void pack8(float4 a, float4 b, uint4& h, uint4& l){
    packp(a.x,a.y,h.x,l.x); packp(a.z,a.w,h.y,l.y);
    packp(b.x,b.y,h.z,l.z); packp(b.z,b.w,h.w,l.w);
}
__device__ __forceinline__ void red_v2(float* p, float a, float b){
    asm volatile("red.global.add.v2.f32 [%0], {%1,%2};" :: "l"(p), "f"(a), "f"(b) : "memory");
}
__device__ __forceinline__ void red_v4(float* p, float a, float b, float c, float d){
    asm volatile("red.global.add.v4.f32 [%0], {%1,%2,%3,%4};" :: "l"(p), "f"(a), "f"(b), "f"(c), "f"(d) : "memory");
}

__global__ void zero_kernel(){
    const int total = N_NODES * HID + N_NODES * 4;
    int i = blockIdx.x * blockDim.x + threadIdx.x;
    if (i < total) { if (i < N_NODES*HID) g_aggr[i] = 0.f; else g_cacc[i - N_NODES*HID] = 0.f; }
}
__global__ void prep_kernel(const float* __restrict__ eW1, const float* __restrict__ eW2, const float* __restrict__ cW1){
    int i = blockIdx.x * 256 + threadIdx.x;
    if (i < 128*320){ int n = i/320, k = i%320; g_e1t[i] = eW1[k*128 + n]; }
    int j = i - 128*320;
    if (j >= 0 && j < 128*128){ int n = j/128, k = j%128; g_e2t[j] = eW2[k*128 + n]; }
    int l = i - 128*320 - 128*128;
    if (l >= 0 && l < 64*128){ int n = l/128, k = l%128; g_c1t[l] = cW1[k*64 + n]; }
}

// SMEM map (bytes):
//  [0, 81920): chunk double buffer. slot s at s*40960: Ah(10240) Al Bh Bl  ([128][40] bf16 each)
//              reused: B2h@0 B2l@34816 ([128][136] bf16); B3h@0 B3l@17408 ([64][136])
//  [81920, 151552): H buffer: Hh [128][136] bf16 (34816), Hl at +34816
//  [151552, ...): misc
#define O_H    81920
#define O_MISC 151552
#define SMEM_E (O_MISC + 3072)

__global__ __launch_bounds__(256, 1)
void edge_kernel(const float* __restrict__ node_feat, const int* __restrict__ edge_index,
                 const float* __restrict__ edge_attr, const float* __restrict__ coords,
                 const float* __restrict__ eb1, const float* __restrict__ eb2,
                 const float* __restrict__ cb1, const float* __restrict__ cW2,
                 const float* __restrict__ cb2)
{
    extern __shared__ char smem[];
    const uint32_t sb = smem_u32(smem);
    const int tid = threadIdx.x, wid = tid >> 5, lane = tid & 31;
    const int M0 = (wid >> 1) * 32;
    const int e0 = blockIdx.x * 128;

    int*   ssrc  = (int*)(smem + O_MISC);
    int*   sdst  = ssrc + 128;
    float* eb1s  = (float*)(sdst + 128);
    float* eb2s  = eb1s + 128;
    float* cb1s  = eb2s + 128;
    float* cw2s  = cb1s + 64;
    float* wcoord= cw2s + 64;   // [128]

    if (tid < 128) {
        ssrc[tid] = edge_index[e0 + tid];
        sdst[tid] = edge_index[N_EDGES + e0 + tid];
        wcoord[tid] = 0.f;
    } else {
        int t = tid - 128;
        eb1s[t] = eb1[t]; eb2s[t] = eb2[t];
        if (t < 64) { cb1s[t] = cb1[t]; cw2s[t] = cW2[t]; }
    }
    __syncthreads();

    float acc[2][8][4];
    #pragma unroll
    for (int t = 0; t < 2; t++) for (int j = 0; j < 8; j++) for (int q = 0; q < 4; q++) acc[t][j][q] = 0.f;

    int Nbase = (wid & 1) * 64;
    const int krow = lane & 15, kseg = (lane >> 4) << 3;

    // one k16 step: A/B split tiles; accumulates 3 split products
    auto mma_k16 = [&](uint32_t aH, uint32_t aL, int as, uint32_t bH, uint32_t bL, int bs, int k0){
        const uint32_t kc = (uint32_t)(k0 + kseg) << 1;
        uint32_t ah[2][4], al[2][4];
        #pragma unroll
        for (int t = 0; t < 2; t++) {
            ldmx4(ah[t], aH + (uint32_t)(M0 + t*16 + krow) * as + kc);
            ldmx4(al[t], aL + (uint32_t)(M0 + t*16 + krow) * as + kc);
        }
        #pragma unroll
        for (int j2 = 0; j2 < 4; j2++) {
            uint32_t bh[4], bl[4];
            ldmx4(bh, bH + (uint32_t)(Nbase + j2*16 + krow) * bs + kc);
            ldmx4(bl, bL + (uint32_t)(Nbase + j2*16 + krow) * bs + kc);
            #pragma unroll
            for (int t = 0; t < 2; t++) {
                mma_bf16(acc[t][2*j2],   ah[t], bh[0], bh[2]);
                mma_bf16(acc[t][2*j2],   ah[t], bl[0], bl[2]);
                mma_bf16(acc[t][2*j2],   al[t], bh[0], bh[2]);
                mma_bf16(acc[t][2*j2+1], ah[t], bh[1], bh[3]);
                mma_bf16(acc[t][2*j2+1], ah[t], bl[1], bl[3]);
                mma_bf16(acc[t][2*j2+1], al[t], bh[1], bh[3]);
            }
        }
    };

    // ---- GEMM1 staging ----
    const int sr = tid >> 1, sh = tid & 1;    // row, 16-col half
    float4 fa[4], fb[4];
    auto stage_ld = [&](int c){
        #pragma unroll
        for (int q = 0; q < 4; q++) {
            int g = c*32 + sh*16 + q*4;
            const float* p;
            if (g < 128)      p = node_feat + (size_t)ssrc[sr]*ND + g;
            else if (g < 256) p = node_feat + (size_t)sdst[sr]*ND + (g-128);
            else              p = edge_attr + (size_t)(e0+sr)*ED + (g-256);
            fa[q] = *(const float4*)p;
        }
        const float* pb = g_e1t + (size_t)sr*320 + c*32 + sh*16;
        #pragma unroll
        for (int q = 0; q < 4; q++) fb[q] = *(const float4*)(pb + q*4);
    };
    auto stage_st = [&](int s){
        char* slot = smem + s * 40960;
        const unsigned o = (unsigned)sr*80 + sh*32;
        uint4 h0,l0,h1,l1;
        pack8(fa[0], fa[1], h0, l0); pack8(fa[2], fa[3], h1, l1);
        *(uint4*)(slot + o) = h0;           *(uint4*)(slot + o + 16) = h1;
        *(uint4*)(slot + 10240 + o) = l0;   *(uint4*)(slot + 10240 + o + 16) = l1;
        pack8(fb[0], fb[1], h0, l0); pack8(fb[2], fb[3], h1, l1);
        *(uint4*)(slot + 20480 + o) = h0;   *(uint4*)(slot + 20480 + o + 16) = h1;
        *(uint4*)(slot + 30720 + o) = l0;   *(uint4*)(slot + 30720 + o + 16) = l1;
    };

    // =========== GEMM1: K=320 ===========
    stage_ld(0); stage_st(0);
    __syncthreads();
    for (int c = 0; c < 10; ++c) {
        if (c < 9) stage_ld(c + 1);
        const uint32_t s0 = sb + (c & 1) * 40960;
        mma_k16(s0, s0+10240, 80, s0+20480, s0+30720, 80, 0);
        mma_k16(s0, s0+10240, 80, s0+20480, s0+30720, 80, 16);
        if (c < 9) stage_st((c + 1) & 1);
        __syncthreads();
    }

    const uint32_t Hh = sb + O_H, Hl = Hh + 34816;
    const int rl0 = lane >> 2, cq = (lane & 3) * 2;

    // ---- epilogue1: h1 = silu(D1+b1) -> H ----
    #pragma unroll
    for (int t = 0; t < 2; t++) {
        const int rl = M0 + t*16 + rl0, rh = rl + 8;
        #pragma unroll
        for (int j = 0; j < 8; j++) {
            const int cb = Nbase + j*8 + cq;
            uint32_t h, l;
            packp(silu_f(acc[t][j][0] + eb1s[cb]), silu_f(acc[t][j][1] + eb1s[cb+1]), h, l);
            *(uint32_t*)(smem + O_H + rl*272 + cb*2) = h;
            *(uint32_t*)(smem + O_H + 34816 + rl*272 + cb*2) = l;
            packp(silu_f(acc[t][j][2] + eb1s[cb]), silu_f(acc[t][j][3] + eb1s[cb+1]), h, l);
            *(uint32_t*)(smem + O_H + rh*272 + cb*2) = h;
            *(uint32_t*)(smem + O_H + 34816 + rh*272 + cb*2) = l;
            acc[t][j][0] = acc[t][j][1] = acc[t][j][2] = acc[t][j][3] = 0.f;
        }
    }
    // stage full B2 (eW2t split, [128][136]) — 64 elems per thread
    {
        const float* p = g_e2t + (size_t)sr*128 + sh*64;
        #pragma unroll
        for (int q = 0; q < 8; q++) {
            uint4 h, l;
            pack8(*(const float4*)(p + q*8), *(const float4*)(p + q*8 + 4), h, l);
            *(uint4*)(smem + sr*272 + (sh*64 + q*8)*2) = h;
            *(uint4*)(smem + 34816 + sr*272 + (sh*64 + q*8)*2) = l;
        }
    }
    __syncthreads();

    // =========== GEMM2: msg-pre = h1 @ eW2 (K=128) ===========
    #pragma unroll
    for (int k = 0; k < 8; k++) mma_k16(Hh, Hl, 272, sb, sb + 34816, 272, k*16);
    __syncthreads();

    // ---- epilogue2: msg = silu(D2+b2); red.v2 scatter; msg -> H ----
    #pragma unroll
    for (int t = 0; t < 2; t++) {
        const int rl = M0 + t*16 + rl0, rh = rl + 8;
        float* agl = g_aggr + (size_t)sdst[rl] * HID;
        float* agh = g_aggr + (size_t)sdst[rh] * HID;
        #pragma unroll
        for (int j = 0; j < 8; j++) {
            const int cb = Nbase + j*8 + cq;
            float v0 = silu_f(acc[t][j][0] + eb2s[cb]), v1 = silu_f(acc[t][j][1] + eb2s[cb+1]);
            float v2 = silu_f(acc[t][j][2] + eb2s[cb]), v3 = silu_f(acc[t][j][3] + eb2s[cb+1]);
            red_v2(agl + cb, v0, v1);
            red_v2(agh + cb, v2, v3);
            uint32_t h, l;
            packp(v0, v1, h, l);
            *(uint32_t*)(smem + O_H + rl*272 + cb*2) = h;
            *(uint32_t*)(smem + O_H + 34816 + rl*272 + cb*2) = l;
            packp(v2, v3, h, l);
            *(uint32_t*)(smem + O_H + rh*272 + cb*2) = h;
            *(uint32_t*)(smem + O_H + 34816 + rh*272 + cb*2) = l;
            acc[t][j][0] = acc[t][j][1] = acc[t][j][2] = acc[t][j][3] = 0.f;
        }
    }
    // stage B3 (cW1t split, [64][136]) — 64 elems per thread (128 threads)
    if (tid < 128) {
        const float* p = g_c1t + (size_t)sr*128 + sh*64;
        #pragma unroll
        for (int q = 0; q < 8; q++) {
            uint4 h, l;
            pack8(*(const float4*)(p + q*8), *(const float4*)(p + q*8 + 4), h, l);
            *(uint4*)(smem + sr*272 + (sh*64 + q*8)*2) = h;
            *(uint4*)(smem + 17408 + sr*272 + (sh*64 + q*8)*2) = l;
        }
    }
    __syncthreads();

    // =========== GEMM3: D3 = msg @ cW1 (K=128, N=64) ===========
    Nbase = (wid & 1) * 32;
    {
        #pragma unroll
        for (int k = 0; k < 8; k++) {
            const uint32_t kc = (uint32_t)(k*16 + kseg) << 1;
            uint32_t ah[2][4], al[2][4];
            #pragma unroll
            for (int t = 0; t < 2; t++) {
                ldmx4(ah[t], Hh + (uint32_t)(M0 + t*16 + krow) * 272 + kc);
                ldmx4(al[t], Hl + (uint32_t)(M0 + t*16 + krow) * 272 + kc);
            }
            #pragma unroll
            for (int j2 = 0; j2 < 2; j2++) {
                uint32_t bh[4], bl[4];
                ldmx4(bh, sb + (uint32_t)(Nbase + j2*16 + krow) * 272 + kc);
                ldmx4(bl, sb + 17408 + (uint32_t)(Nbase + j2*16 + krow) * 272 + kc);
                #pragma unroll
                for (int t = 0; t < 2; t++) {
                    mma_bf16(acc[t][2*j2],   ah[t], bh[0], bh[2]);
                    mma_bf16(acc[t][2*j2],   ah[t], bl[0], bl[2]);
                    mma_bf16(acc[t][2*j2],   al[t], bh[0], bh[2]);
                    mma_bf16(acc[t][2*j2+1], ah[t], bh[1], bh[3]);
                    mma_bf16(acc[t][2*j2+1], ah[t], bl[1], bl[3]);
                    mma_bf16(acc[t][2*j2+1], al[t], bh[1], bh[3]);
                }
            }
        }
    }

    // ---- epilogue3: coord weight reduce + scatter ----
    #pragma unroll
    for (int t = 0; t < 2; t++) {
        const int rl = M0 + t*16 + rl0, rh = rl + 8;
        float pl = 0.f, ph = 0.f;
        #pragma unroll
        for (int j = 0; j < 4; j++) {
            const int cb = Nbase + j*8 + cq;
            pl += silu_f(acc[t][j][0] + cb1s[cb]) * cw2s[cb] + silu_f(acc[t][j][1] + cb1s[cb+1]) * cw2s[cb+1];
            ph += silu_f(acc[t][j][2] + cb1s[cb]) * cw2s[cb] + silu_f(acc[t][j][3] + cb1s[cb+1]) * cw2s[cb+1];
        }
        pl += __shfl_xor_sync(0xffffffffu, pl, 1); pl += __shfl_xor_sync(0xffffffffu, pl, 2);
        ph += __shfl_xor_sync(0xffffffffu, ph, 1); ph += __shfl_xor_sync(0xffffffffu, ph, 2);
        if ((lane & 3) == 0) { atomicAdd(&wcoord[rl], pl); atomicAdd(&wcoord[rh], ph); }
    }
    __syncthreads();
    if (tid < 128) {
        const float w0 = wcoord[tid] + __ldg(cb2);
        const int is = ssrc[tid], id = sdst[tid];
        const float dx = coords[is*3+0] - coords[id*3+0];
        const float dy = coords[is*3+1] - coords[id*3+1];
        const float dz = coords[is*3+2] - coords[id*3+2];
        const float w = w0 / (sqrtf(dx*dx + dy*dy + dz*dz) + 1e-8f);
        red_v4(&g_cacc[(size_t)id * 4], dx * w, dy * w, dz * w, 0.0f);
    }
}

// ---------------- node kernel (f32x2, known-good) ----------------
__device__ __forceinline__ u64 splat2(float a){ u64 r; asm("mov.b64 %0, {%1, %1};" : "=l"(r) : "f"(a)); return r; }
__device__ __forceinline__ void fma2(u64& d, u64 a, u64 b){ asm("fma.rn.f32x2 %0, %1, %2, %3;" : "=l"(d) : "l"(a), "l"(b), "l"(d)); }
__device__ __forceinline__ float2 unpack2(u64 v){ float2 f; asm("mov.b64 {%0, %1}, %2;" : "=f"(f.x), "=f"(f.y) : "l"(v)); return f; }

#define TILE_N 64
#define KC 32
#define KC_PAD 36
struct __align__(16) NodeSmem {
    float As[2][TILE_N][KC_PAD];
    float Bs[2][KC][HID];
    float Hs[TILE_N][HID + 4];
    float nb1[HID];
    float nb2[HID];
};

__global__ __launch_bounds__(256, 1)
void node_kernel(const float* __restrict__ node_feat, const float* __restrict__ coords,
                 const float* __restrict__ nW1, const float* __restrict__ nb1,
                 const float* __restrict__ nW2, const float* __restrict__ nb2,
                 float* __restrict__ out)
{
    extern __shared__ char smem_raw[];
    NodeSmem& sm = *reinterpret_cast<NodeSmem*>(smem_raw);
    const int tid = threadIdx.x, tx = tid & 15, ty = tid >> 4;
    const int n0 = blockIdx.x * TILE_N;

    if (tid < HID) { sm.nb1[tid] = nb1[tid]; sm.nb2[tid] = nb2[tid]; }
    __syncthreads();

    const int se = tid >> 2, sq = tid & 3;
    float4 ra[2];
    auto ldA = [&](int kb){
        const int kg = kb + sq * 8;
        const int node = min(n0 + se, N_NODES - 1);
        const float* p = (kg < ND) ? node_feat + (size_t)node * ND + kg
                                   : g_aggr + (size_t)node * HID + (kg - ND);
        ra[0] = *(const float4*)(p); ra[1] = *(const float4*)(p + 4);
    };
    auto stA = [&](int buf){
        float* q = &sm.As[buf][se][sq * 8];
        *(float4*)(q) = ra[0]; *(float4*)(q + 4) = ra[1];
    };
    float4 rb[4];
    auto ldB = [&](const float* W, int kb){
        #pragma unroll
        for (int r = 0; r < 4; r++) {
            const int f = tid + r * 256, k = f >> 5, n4 = f & 31;
            rb[r] = *(const float4*)(W + (size_t)(kb + k) * HID + n4 * 4);
        }
    };
    auto stB = [&](int buf){
        #pragma unroll
        for (int r = 0; r < 4; r++) {
            const int f = tid + r * 256, k = f >> 5, n4 = f & 31;
            *(float4*)(&sm.Bs[buf][k][n4 * 4]) = rb[r];
        }
    };

    u64 acc[4][4];
    #pragma unroll
    for (int i = 0; i < 4; i++) for (int j = 0; j < 4; j++) acc[i][j] = 0ull;
    ldA(0); ldB(nW1, 0); stA(0); stB(0);
    __syncthreads();
    const int NC1 = (ND + HID) / KC;
    for (int c = 0; c < NC1; ++c) {
        const int cur = c & 1;
        if (c + 1 < NC1) { ldA((c + 1) * KC); ldB(nW1, (c + 1) * KC); }
        #pragma unroll 4
        for (int kk = 0; kk < KC; ++kk) {
            ulonglong2 b01 = *(const ulonglong2*)&sm.Bs[cur][kk][tx * 8];
            ulonglong2 b23 = *(const ulonglong2*)&sm.Bs[cur][kk][tx * 8 + 4];
            #pragma unroll
            for (int i = 0; i < 4; i++) {
                u64 ap = splat2(sm.As[cur][ty * 4 + i][kk]);
                fma2(acc[i][0], ap, b01.x); fma2(acc[i][1], ap, b01.y);
                fma2(acc[i][2], ap, b23.x); fma2(acc[i][3], ap, b23.y);
            }
        }
        if (c + 1 < NC1) { stA((c + 1) & 1); stB((c + 1) & 1); }
        __syncthreads();
    }
    #pragma unroll
    for (int i = 0; i < 4; i++) {
        const int e = ty * 4 + i;
        #pragma unroll
        for (int j = 0; j < 4; j++) {
            const int n = tx * 8 + j * 2;
            float2 v = unpack2(acc[i][j]);
            v.x = silu_f(v.x + sm.nb1[n]); v.y = silu_f(v.y + sm.nb1[n + 1]);
            *(float2*)&sm.Hs[e][n] = v;
        }
    }
    u64 acc2[4][4];
    #pragma unroll
    for (int i = 0; i < 4; i++) for (int j = 0; j < 4; j++) acc2[i][j] = 0ull;
    ldB(nW2, 0); stB(0);
    __syncthreads();
    const int NC2 = HID / KC;
    for (int c = 0; c < NC2; ++c) {
        const int cur = c & 1;
        if (c + 1 < NC2) ldB(nW2, (c + 1) * KC);
        const int kb = c * KC;
        #pragma unroll 4
        for (int kk = 0; kk < KC; ++kk) {
            ulonglong2 b01 = *(const ulonglong2*)&sm.Bs[cur][kk][tx * 8];
            ulonglong2 b23 = *(const ulonglong2*)&sm.Bs[cur][kk][tx * 8 + 4];
            #pragma unroll
            for (int i = 0; i < 4; i++) {
                u64 ap = splat2(sm.Hs[ty * 4 + i][kb + kk]);
                fma2(acc2[i][0], ap, b01.x); fma2(acc2[i][1], ap, b01.y);
                fma2(acc2[i][2], ap, b23.x); fma2(acc2[i][3], ap, b23.y);
            }
        }
        if (c + 1 < NC2) stB((c + 1) & 1);
        __syncthreads();
    }
    #pragma unroll
    for (int i = 0; i < 4; i++) {
        const int node = n0 + ty * 4 + i;
        if (node < N_NODES) {
            #pragma unroll
            for (int j = 0; j < 4; j++) {
                const int n = tx * 8 + j * 2;
                float2 v = unpack2(acc2[i][j]);
                out[(size_t)node * ND + n]     = v.x + sm.nb2[n]     + node_feat[(size_t)node * ND + n];
                out[(size_t)node * ND + n + 1] = v.y + sm.nb2[n + 1] + node_feat[(size_t)node * ND + n + 1];
            }
        }
    }
    for (int idx = tid; idx < TILE_N * 3; idx += 256) {
        const int node = n0 + idx / 3, c = idx % 3;
        if (node < N_NODES)
            out[(size_t)N_NODES * ND + node * 3 + c] = coords[node * 3 + c] + g_cacc[(size_t)node * 4 + c];
    }
}

extern "C" void kernel_launch(void* const* d_in, const int* in_sizes, int n_in,
                              void* d_out, int out_size)
{
    const float* node_feat  = (const float*)d_in[0];
    const int*   edge_index = (const int*)  d_in[1];
    const float* edge_attr  = (const float*)d_in[2];
    const float* coords     = (const float*)d_in[3];
    const float* eW1 = (const float*)d_in[4];
    const float* eb1 = (const float*)d_in[5];
    const float* eW2 = (const float*)d_in[6];
    const float* eb2 = (const float*)d_in[7];
    const float* nW1 = (const float*)d_in[8];
    const float* nb1 = (const float*)d_in[9];
    const float* nW2 = (const float*)d_in[10];
    const float* nb2 = (const float*)d_in[11];
    const float* cW1 = (const float*)d_in[12];
    const float* cb1 = (const float*)d_in[13];
    const float* cW2 = (const float*)d_in[14];
    const float* cb2 = (const float*)d_in[15];
    float* out = (float*)d_out;

    cudaFuncSetAttribute(edge_kernel, cudaFuncAttributeMaxDynamicSharedMemorySize, (int)SMEM_E);
    cudaFuncSetAttribute(node_kernel, cudaFuncAttributeMaxDynamicSharedMemorySize, (int)sizeof(NodeSmem));

    const int ztotal = N_NODES * HID + N_NODES * 4;
    zero_kernel<<<(ztotal + 255) / 256, 256>>>();
    prep_kernel<<<(128*320 + 128*128 + 64*128 + 255) / 256, 256>>>(eW1, eW2, cW1);

    edge_kernel<<<N_EDGES / 128, 256, SMEM_E>>>(
        node_feat, edge_index, edge_attr, coords, eb1, eb2, cb1, cW2, cb2);

    node_kernel<<<(N_NODES + TILE_N - 1) / TILE_N, 256, sizeof(NodeSmem)>>>(
        node_feat, coords, nW1, nb1, nW2, nb2, out);
}